// round 15
// baseline (speedup 1.0000x reference)
#include <cuda_runtime.h>
#include <cuda_fp16.h>
#include <cstdint>

// ---------------------------------------------------------------------------
// GCN_dgl R13: R12 (scan-free buckets, HMMA, fp16 intermediates, tail-free
// gather) + u16 CSR indices (8 per LDG.128) + dense<0> made graph-independent
// (per-edge ns in gather<0>) and overlapped with the idle-issue fill chain.
// ---------------------------------------------------------------------------

constexpr int NN  = 50000;
constexpr int NE  = 800000;
constexpr int D   = 96;
constexpr int DH4 = D / 4;                 // 24 8B-lanes per fp16 row
constexpr int LDS = 104;                   // smem half-stride for MMA tiles
constexpr int CAP = 128;                   // bucket capacity (max in-deg ~45)

struct alignas(8) h4 { __half2 lo, hi; };

// Scratch (allocation-free __device__ globals; zero-initialized at load)
__device__ int          g_degi_out[NN];
__device__ float        g_norm_src[NN + 1];   // [NN] stays 0 forever (dummy row)
__device__ float        g_norm_dst[NN];
__device__ int          g_fill[NN];           // slot counter == in-degree
__device__ alignas(16) unsigned short g_csr[(size_t)NN * CAP];
__device__ __half       g_xw[(size_t)(NN + 1) * D];  // row NN: permanent zeros
__device__ __half       g_h1[(size_t)(NN + 1) * D];  // row NN: permanent zeros
__device__ unsigned int g_max[D];

// --- mma/ldmatrix primitives --------------------------------------------------
__device__ __forceinline__ void ldsm_x4(uint32_t& r0, uint32_t& r1, uint32_t& r2,
                                        uint32_t& r3, uint32_t addr) {
    asm volatile("ldmatrix.sync.aligned.m8n8.x4.shared.b16 {%0,%1,%2,%3}, [%4];"
                 : "=r"(r0), "=r"(r1), "=r"(r2), "=r"(r3) : "r"(addr));
}
__device__ __forceinline__ void ldsm_x2_trans(uint32_t& r0, uint32_t& r1, uint32_t addr) {
    asm volatile("ldmatrix.sync.aligned.m8n8.x2.trans.shared.b16 {%0,%1}, [%2];"
                 : "=r"(r0), "=r"(r1) : "r"(addr));
}
__device__ __forceinline__ void mma16816(float& d0, float& d1, float& d2, float& d3,
                                         uint32_t a0, uint32_t a1, uint32_t a2,
                                         uint32_t a3, uint32_t b0, uint32_t b1) {
    asm volatile(
        "mma.sync.aligned.m16n8k16.row.col.f32.f16.f16.f32 "
        "{%0,%1,%2,%3},{%4,%5,%6,%7},{%8,%9},{%0,%1,%2,%3};"
        : "+f"(d0), "+f"(d1), "+f"(d2), "+f"(d3)
        : "r"(a0), "r"(a1), "r"(a2), "r"(a3), "r"(b0), "r"(b1));
}

// --- single edge pass: bucket slot allocation + both degree counts --------------
__global__ void fill_kernel(const int* __restrict__ src, const int* __restrict__ dst) {
    int e = blockIdx.x * blockDim.x + threadIdx.x;
    if (e < NE) {
        int s = src[e];
        int d = dst[e];
        int pos = atomicAdd(&g_fill[d], 1);            // counter == in-degree
        if (pos < CAP) g_csr[(size_t)d * CAP + pos] = (unsigned short)s;
        atomicAdd(&g_degi_out[s], 1);                  // out-degree for norm_src
    }
}

// --- norms from the counters + pad dummy slots to a multiple of 8 ---------------
__global__ void norm_pad_kernel() {
    int i = blockIdx.x * blockDim.x + threadIdx.x;
    if (i < D) g_max[i] = 0u;                 // consumed by gather<1> (later)
    if (i < NN) {
        int dI = g_fill[i]; if (dI > CAP) dI = CAP;
        int dO = g_degi_out[i];
        g_norm_src[i] = (dO > 0) ? rsqrtf((float)dO) : 1.0f;
        g_norm_dst[i] = (dI > 0) ? rsqrtf((float)dI) : 1.0f;
        int pdeg = (dI + 7) & ~7;             // pad [dI, pdeg) with zero-row idx
        size_t base = (size_t)i * CAP;
        for (int s = dI; s < pdeg; s++) g_csr[base + s] = (unsigned short)NN;
    }
}

// --- tensor-core dense GEMM: out_h = in @ W (plain; no epilogue scaling) ---------
// MODE 0: fp32 input (x). MODE 1: fp16 input (h1).
template <int MODE>
__global__ void __launch_bounds__(128)
dense_mma(const void* __restrict__ in_, const float* __restrict__ W,
          __half* __restrict__ out) {
    __shared__ alignas(16) __half Bs[96 * LDS];
    __shared__ alignas(16) __half As[4][16 * LDS];

    int tid = threadIdx.x, wid = tid >> 5, lane = tid & 31;

    for (int c = tid; c < 96 * 12; c += 128) {
        int r = c / 12, c8 = c % 12;
        const float4* wp = (const float4*)(W + r * 96 + c8 * 8);
        float4 f0 = wp[0], f1 = wp[1];
        __half hb[8] = {__float2half_rn(f0.x), __float2half_rn(f0.y),
                        __float2half_rn(f0.z), __float2half_rn(f0.w),
                        __float2half_rn(f1.x), __float2half_rn(f1.y),
                        __float2half_rn(f1.z), __float2half_rn(f1.w)};
        *(uint4*)&Bs[r * LDS + c8 * 8] = *(uint4*)hb;
    }

    int rowBase = blockIdx.x * 64 + wid * 16;
    for (int c = lane; c < 16 * 12; c += 32) {
        int r = c / 12, c8 = c % 12;
        int n = rowBase + r;
        __half hb[8];
        if (n < NN) {
            if (MODE == 0) {
                const float4* xp = (const float4*)((const float*)in_ + (size_t)n * D + c8 * 8);
                float4 f0 = xp[0], f1 = xp[1];
                hb[0] = __float2half_rn(f0.x); hb[1] = __float2half_rn(f0.y);
                hb[2] = __float2half_rn(f0.z); hb[3] = __float2half_rn(f0.w);
                hb[4] = __float2half_rn(f1.x); hb[5] = __float2half_rn(f1.y);
                hb[6] = __float2half_rn(f1.z); hb[7] = __float2half_rn(f1.w);
            } else {
                *(uint4*)hb = *(const uint4*)((const __half*)in_ + (size_t)n * D + c8 * 8);
            }
        } else {
            #pragma unroll
            for (int q = 0; q < 8; q++) hb[q] = __float2half_rn(0.f);
        }
        *(uint4*)&As[wid][r * LDS + c8 * 8] = *(uint4*)hb;
    }
    __syncthreads();

    float d[12][4];
    #pragma unroll
    for (int j = 0; j < 12; j++) { d[j][0] = d[j][1] = d[j][2] = d[j][3] = 0.f; }

    uint32_t aBase = (uint32_t)__cvta_generic_to_shared(&As[wid][0]);
    uint32_t bBase = (uint32_t)__cvta_generic_to_shared(&Bs[0]);

    #pragma unroll
    for (int k = 0; k < 6; k++) {
        uint32_t a0, a1, a2, a3;
        uint32_t aAddr = aBase + (uint32_t)(((lane & 15) * LDS + (lane >> 4) * 8 + k * 16) * 2);
        ldsm_x4(a0, a1, a2, a3, aAddr);
        #pragma unroll
        for (int j = 0; j < 12; j++) {
            uint32_t b0, b1;
            uint32_t bAddr = bBase + (uint32_t)(((k * 16 + (lane & 15)) * LDS + j * 8) * 2);
            ldsm_x2_trans(b0, b1, bAddr);
            mma16816(d[j][0], d[j][1], d[j][2], d[j][3], a0, a1, a2, a3, b0, b1);
        }
    }

    int g = lane >> 2, q = lane & 3;
    int r0 = rowBase + g, r1 = rowBase + g + 8;
    #pragma unroll
    for (int j = 0; j < 12; j++) {
        int col = j * 8 + q * 2;
        if (r0 < NN)
            *(__half2*)&out[(size_t)r0 * D + col] = __floats2half2_rn(d[j][0], d[j][1]);
        if (r1 < NN)
            *(__half2*)&out[(size_t)r1 * D + col] = __floats2half2_rn(d[j][2], d[j][3]);
    }
}

// --- tail-free bucket gather (u16 indices: 8 per LDG.128) + layer epilogue -------
// EPI 0: agg = sum ns[s]*in[s];  out[n] = relu(agg*nd + b) * ns[n]   (fp16)
// EPI 1: agg = sum in[s] (pre-scaled); relu -> smem max -> global atomicMax
template <int EPI>
__global__ void __launch_bounds__(256)
gather_kernel(const h4* __restrict__ in, const float4* __restrict__ b,
              h4* __restrict__ out) {
    __shared__ unsigned int smax[D];
    int t = threadIdx.x;
    if (EPI == 1) {
        if (t < D) smax[t] = 0u;
        __syncthreads();
    }

    int n    = (blockIdx.x * 256 + t) >> 5;
    int lane = t & 31;

    if (n < NN && lane < DH4) {
        int dI = g_fill[n]; if (dI > CAP) dI = CAP;
        int pdeg = (dI + 7) & ~7;
        const unsigned short* bucket = g_csr + (size_t)n * CAP;
        float4 a = make_float4(0.f, 0.f, 0.f, 0.f);

        for (int p = 0; p < pdeg; p += 8) {      // 8 u16 indices = one LDG.128
            uint4 q = *(const uint4*)(bucket + p);
            int s[8] = {(int)(q.x & 0xffffu), (int)(q.x >> 16),
                        (int)(q.y & 0xffffu), (int)(q.y >> 16),
                        (int)(q.z & 0xffffu), (int)(q.z >> 16),
                        (int)(q.w & 0xffffu), (int)(q.w >> 16)};
            h4 r[8];
            #pragma unroll
            for (int i = 0; i < 8; i++) r[i] = in[s[i] * DH4 + lane];
            if (EPI == 0) {
                float nsv[8];
                #pragma unroll
                for (int i = 0; i < 8; i++) nsv[i] = g_norm_src[s[i]];
                #pragma unroll
                for (int i = 0; i < 8; i++) {
                    float2 f0 = __half22float2(r[i].lo);
                    float2 f1 = __half22float2(r[i].hi);
                    a.x = fmaf(f0.x, nsv[i], a.x);
                    a.y = fmaf(f0.y, nsv[i], a.y);
                    a.z = fmaf(f1.x, nsv[i], a.z);
                    a.w = fmaf(f1.y, nsv[i], a.w);
                }
            } else {
                #pragma unroll
                for (int i = 0; i < 8; i++) {
                    float2 f0 = __half22float2(r[i].lo);
                    float2 f1 = __half22float2(r[i].hi);
                    a.x += f0.x; a.y += f0.y; a.z += f1.x; a.w += f1.y;
                }
            }
        }

        float  nd = g_norm_dst[n];
        float4 bv = b[lane];
        float v0 = fmaxf(fmaf(a.x, nd, bv.x), 0.f);
        float v1 = fmaxf(fmaf(a.y, nd, bv.y), 0.f);
        float v2 = fmaxf(fmaf(a.z, nd, bv.z), 0.f);
        float v3 = fmaxf(fmaf(a.w, nd, bv.w), 0.f);

        if (EPI == 0) {
            float ns = g_norm_src[n];            // pre-scale for layer-2 gather
            h4 o;
            o.lo = __floats2half2_rn(v0 * ns, v1 * ns);
            o.hi = __floats2half2_rn(v2 * ns, v3 * ns);
            out[n * DH4 + lane] = o;
        } else {
            // non-negative floats: uint ordering == float ordering
            atomicMax(&smax[4 * lane + 0], __float_as_uint(v0));
            atomicMax(&smax[4 * lane + 1], __float_as_uint(v1));
            atomicMax(&smax[4 * lane + 2], __float_as_uint(v2));
            atomicMax(&smax[4 * lane + 3], __float_as_uint(v3));
        }
    }

    if (EPI == 1) {
        __syncthreads();
        if (t < D) atomicMax(&g_max[t], smax[t]);
    }
}

// --- head: out[1,2] = gmax @ Wl + bl ----------------------------------------------
__global__ void final_kernel(const float* __restrict__ Wl,
                             const float* __restrict__ bl,
                             float* __restrict__ out) {
    int c = threadIdx.x;
    if (c < 2) {
        float acc = bl[c];
        #pragma unroll 8
        for (int k = 0; k < D; k++)
            acc += __uint_as_float(g_max[k]) * Wl[k * 2 + c];
        out[c] = acc;
    }
}

// --- side stream + events (host objects, created once at static init) --------------
struct Aux {
    cudaStream_t s2  = nullptr;
    cudaEvent_t  evF = nullptr, evJ = nullptr;
    bool ok = false;
    Aux() {
        if (cudaStreamCreateWithFlags(&s2, cudaStreamNonBlocking) == cudaSuccess &&
            cudaEventCreateWithFlags(&evF, cudaEventDisableTiming) == cudaSuccess &&
            cudaEventCreateWithFlags(&evJ, cudaEventDisableTiming) == cudaSuccess)
            ok = true;
    }
};
static Aux g_aux;

extern "C" void kernel_launch(void* const* d_in, const int* in_sizes, int n_in,
                              void* d_out, int out_size) {
    const float* x   = (const float*)d_in[0];
    const int*   src = (const int*)  d_in[1];
    const int*   dst = (const int*)  d_in[2];
    const float* W1  = (const float*)d_in[3];
    const float* b1  = (const float*)d_in[4];
    const float* W2  = (const float*)d_in[5];
    const float* b2  = (const float*)d_in[6];
    const float* Wl  = (const float*)d_in[7];
    const float* bl  = (const float*)d_in[8];
    float* out = (float*)d_out;

    void *pxw, *ph1, *pdo, *pfill;
    cudaGetSymbolAddress(&pxw,   g_xw);
    cudaGetSymbolAddress(&ph1,   g_h1);
    cudaGetSymbolAddress(&pdo,   g_degi_out);
    cudaGetSymbolAddress(&pfill, g_fill);
    __half* xw = (__half*)pxw;
    __half* h1 = (__half*)ph1;

    int mblocks = (NN + 63) / 64;
    int gblocks = (NN * 32 + 255) / 256;

    // Fork: x@W1 is fully graph-independent (ns applied per-edge in gather<0>)
    // -> overlap with fill chain, whose issue utilization is ~4% (idle SMs).
    bool fork = g_aux.ok;
    if (fork) {
        cudaEventRecord(g_aux.evF, 0);
        cudaStreamWaitEvent(g_aux.s2, g_aux.evF, 0);
        dense_mma<0><<<mblocks, 128, 0, g_aux.s2>>>(x, W1, xw);
        cudaEventRecord(g_aux.evJ, g_aux.s2);
    } else {
        dense_mma<0><<<mblocks, 128>>>(x, W1, xw);
    }

    // Scan-free CSR build: one edge pass + one node pass (main stream)
    cudaMemsetAsync(pdo,   0, NN * sizeof(int));
    cudaMemsetAsync(pfill, 0, NN * sizeof(int));
    fill_kernel    <<<(NE + 255) / 256, 256>>>(src, dst);
    norm_pad_kernel<<<(NN + 255) / 256, 256>>>();

    if (fork) cudaStreamWaitEvent(0, g_aux.evJ, 0);

    // Layer 1: h1 = relu(nd * sum_s ns[s]*xw[s] + b1) * ns   (fp16)
    gather_kernel<0><<<gblocks, 256>>>((const h4*)xw, (const float4*)b1, (h4*)h1);
    // Layer 2: xw = h1@W2 (HMMA); gather + fused maxpool
    dense_mma<1><<<mblocks, 128>>>(h1, W2, xw);
    gather_kernel<1><<<gblocks, 256>>>((const h4*)xw, (const float4*)b2, nullptr);

    final_kernel<<<1, 32>>>(Wl, bl, out);
}

// round 16
// speedup vs baseline: 1.1432x; 1.1432x over previous
#include <cuda_runtime.h>
#include <cuda_fp16.h>
#include <cstdint>

// ---------------------------------------------------------------------------
// GCN_dgl R14: R12 dataflow (scan-free u16 buckets, HMMA dense with ns
// epilogue, fp16 intermediates, pure-add tail-free gather, no fork)
// + full-lane gather mapping: one thread per (node, h4-lane), n = gid/24.
// ---------------------------------------------------------------------------

constexpr int NN  = 50000;
constexpr int NE  = 800000;
constexpr int D   = 96;
constexpr int DH4 = D / 4;                 // 24 8B-lanes per fp16 row
constexpr int LDS = 104;                   // smem half-stride for MMA tiles
constexpr int CAP = 128;                   // bucket capacity (max in-deg ~45)

struct alignas(8) h4 { __half2 lo, hi; };

// Scratch (allocation-free __device__ globals; zero-initialized at load)
__device__ int          g_degi_out[NN];
__device__ float        g_norm_src[NN + 1];   // [NN] stays 0 forever (dummy row)
__device__ float        g_norm_dst[NN];
__device__ int          g_fill[NN];           // slot counter == in-degree
__device__ alignas(16) unsigned short g_csr[(size_t)NN * CAP];
__device__ __half       g_xw[(size_t)(NN + 1) * D];  // row NN: permanent zeros
__device__ __half       g_h1[(size_t)(NN + 1) * D];  // row NN: permanent zeros
__device__ unsigned int g_max[D];

// --- mma/ldmatrix primitives --------------------------------------------------
__device__ __forceinline__ void ldsm_x4(uint32_t& r0, uint32_t& r1, uint32_t& r2,
                                        uint32_t& r3, uint32_t addr) {
    asm volatile("ldmatrix.sync.aligned.m8n8.x4.shared.b16 {%0,%1,%2,%3}, [%4];"
                 : "=r"(r0), "=r"(r1), "=r"(r2), "=r"(r3) : "r"(addr));
}
__device__ __forceinline__ void ldsm_x2_trans(uint32_t& r0, uint32_t& r1, uint32_t addr) {
    asm volatile("ldmatrix.sync.aligned.m8n8.x2.trans.shared.b16 {%0,%1}, [%2];"
                 : "=r"(r0), "=r"(r1) : "r"(addr));
}
__device__ __forceinline__ void mma16816(float& d0, float& d1, float& d2, float& d3,
                                         uint32_t a0, uint32_t a1, uint32_t a2,
                                         uint32_t a3, uint32_t b0, uint32_t b1) {
    asm volatile(
        "mma.sync.aligned.m16n8k16.row.col.f32.f16.f16.f32 "
        "{%0,%1,%2,%3},{%4,%5,%6,%7},{%8,%9},{%0,%1,%2,%3};"
        : "+f"(d0), "+f"(d1), "+f"(d2), "+f"(d3)
        : "r"(a0), "r"(a1), "r"(a2), "r"(a3), "r"(b0), "r"(b1));
}

// --- single edge pass: bucket slot allocation + both degree counts --------------
__global__ void fill_kernel(const int* __restrict__ src, const int* __restrict__ dst) {
    int e = blockIdx.x * blockDim.x + threadIdx.x;
    if (e < NE) {
        int s = src[e];
        int d = dst[e];
        int pos = atomicAdd(&g_fill[d], 1);            // counter == in-degree
        if (pos < CAP) g_csr[(size_t)d * CAP + pos] = (unsigned short)s;
        atomicAdd(&g_degi_out[s], 1);                  // out-degree for norm_src
    }
}

// --- norms from the counters + pad dummy slots to a multiple of 8 ---------------
__global__ void norm_pad_kernel() {
    int i = blockIdx.x * blockDim.x + threadIdx.x;
    if (i < D) g_max[i] = 0u;                 // consumed by gather<1> (later)
    if (i < NN) {
        int dI = g_fill[i]; if (dI > CAP) dI = CAP;
        int dO = g_degi_out[i];
        g_norm_src[i] = (dO > 0) ? rsqrtf((float)dO) : 1.0f;
        g_norm_dst[i] = (dI > 0) ? rsqrtf((float)dI) : 1.0f;
        int pdeg = (dI + 7) & ~7;             // pad [dI, pdeg) with zero-row idx
        size_t base = (size_t)i * CAP;
        for (int s = dI; s < pdeg; s++) g_csr[base + s] = (unsigned short)NN;
    }
}

// --- tensor-core dense GEMM: out_h = (in @ W) [* norm_src] -----------------------
// MODE 0: fp32 input (x), epilogue scales rows by norm_src. MODE 1: fp16 input.
template <int MODE>
__global__ void __launch_bounds__(128)
dense_mma(const void* __restrict__ in_, const float* __restrict__ W,
          __half* __restrict__ out) {
    __shared__ alignas(16) __half Bs[96 * LDS];
    __shared__ alignas(16) __half As[4][16 * LDS];

    int tid = threadIdx.x, wid = tid >> 5, lane = tid & 31;

    for (int c = tid; c < 96 * 12; c += 128) {
        int r = c / 12, c8 = c % 12;
        const float4* wp = (const float4*)(W + r * 96 + c8 * 8);
        float4 f0 = wp[0], f1 = wp[1];
        __half hb[8] = {__float2half_rn(f0.x), __float2half_rn(f0.y),
                        __float2half_rn(f0.z), __float2half_rn(f0.w),
                        __float2half_rn(f1.x), __float2half_rn(f1.y),
                        __float2half_rn(f1.z), __float2half_rn(f1.w)};
        *(uint4*)&Bs[r * LDS + c8 * 8] = *(uint4*)hb;
    }

    int rowBase = blockIdx.x * 64 + wid * 16;
    for (int c = lane; c < 16 * 12; c += 32) {
        int r = c / 12, c8 = c % 12;
        int n = rowBase + r;
        __half hb[8];
        if (n < NN) {
            if (MODE == 0) {
                const float4* xp = (const float4*)((const float*)in_ + (size_t)n * D + c8 * 8);
                float4 f0 = xp[0], f1 = xp[1];
                hb[0] = __float2half_rn(f0.x); hb[1] = __float2half_rn(f0.y);
                hb[2] = __float2half_rn(f0.z); hb[3] = __float2half_rn(f0.w);
                hb[4] = __float2half_rn(f1.x); hb[5] = __float2half_rn(f1.y);
                hb[6] = __float2half_rn(f1.z); hb[7] = __float2half_rn(f1.w);
            } else {
                *(uint4*)hb = *(const uint4*)((const __half*)in_ + (size_t)n * D + c8 * 8);
            }
        } else {
            #pragma unroll
            for (int q = 0; q < 8; q++) hb[q] = __float2half_rn(0.f);
        }
        *(uint4*)&As[wid][r * LDS + c8 * 8] = *(uint4*)hb;
    }
    __syncthreads();

    float d[12][4];
    #pragma unroll
    for (int j = 0; j < 12; j++) { d[j][0] = d[j][1] = d[j][2] = d[j][3] = 0.f; }

    uint32_t aBase = (uint32_t)__cvta_generic_to_shared(&As[wid][0]);
    uint32_t bBase = (uint32_t)__cvta_generic_to_shared(&Bs[0]);

    #pragma unroll
    for (int k = 0; k < 6; k++) {
        uint32_t a0, a1, a2, a3;
        uint32_t aAddr = aBase + (uint32_t)(((lane & 15) * LDS + (lane >> 4) * 8 + k * 16) * 2);
        ldsm_x4(a0, a1, a2, a3, aAddr);
        #pragma unroll
        for (int j = 0; j < 12; j++) {
            uint32_t b0, b1;
            uint32_t bAddr = bBase + (uint32_t)(((k * 16 + (lane & 15)) * LDS + j * 8) * 2);
            ldsm_x2_trans(b0, b1, bAddr);
            mma16816(d[j][0], d[j][1], d[j][2], d[j][3], a0, a1, a2, a3, b0, b1);
        }
    }

    int g = lane >> 2, q = lane & 3;
    int r0 = rowBase + g, r1 = rowBase + g + 8;
    float ns0 = 1.f, ns1 = 1.f;
    if (MODE == 0) {
        if (r0 < NN) ns0 = g_norm_src[r0];
        if (r1 < NN) ns1 = g_norm_src[r1];
    }
    #pragma unroll
    for (int j = 0; j < 12; j++) {
        int col = j * 8 + q * 2;
        if (r0 < NN)
            *(__half2*)&out[(size_t)r0 * D + col] = __floats2half2_rn(d[j][0] * ns0, d[j][1] * ns0);
        if (r1 < NN)
            *(__half2*)&out[(size_t)r1 * D + col] = __floats2half2_rn(d[j][2] * ns1, d[j][3] * ns1);
    }
}

// --- full-lane tail-free bucket gather + layer epilogue --------------------------
// One THREAD per (node, h4-lane): n = gid/24, l = gid%24 -> no idle lanes.
// Buckets padded to multiples of 8 with dummy index NN (permanently-zero row).
// EPI 0: out[n] = relu(agg*nd + b) * ns[n]  (fp16, pre-scaled for layer 2)
// EPI 1: relu(agg*nd + b) -> block smem max -> global atomicMax
template <int EPI>
__global__ void __launch_bounds__(256)
gather_kernel(const h4* __restrict__ in, const float4* __restrict__ b,
              h4* __restrict__ out) {
    __shared__ unsigned int smax[D];
    int t = threadIdx.x;
    if (EPI == 1) {
        if (t < D) smax[t] = 0u;
        __syncthreads();
    }

    int gid = blockIdx.x * 256 + t;
    int n   = gid / DH4;                     // 24 threads per node
    int l   = gid - n * DH4;

    if (n < NN) {
        int dI = g_fill[n]; if (dI > CAP) dI = CAP;
        int pdeg = (dI + 7) & ~7;
        const unsigned short* bucket = g_csr + (size_t)n * CAP;
        float4 a = make_float4(0.f, 0.f, 0.f, 0.f);

        for (int p = 0; p < pdeg; p += 8) {      // 8 u16 indices = one LDG.128
            uint4 q = *(const uint4*)(bucket + p);
            int s[8] = {(int)(q.x & 0xffffu), (int)(q.x >> 16),
                        (int)(q.y & 0xffffu), (int)(q.y >> 16),
                        (int)(q.z & 0xffffu), (int)(q.z >> 16),
                        (int)(q.w & 0xffffu), (int)(q.w >> 16)};
            h4 r[8];
            #pragma unroll
            for (int i = 0; i < 8; i++) r[i] = in[s[i] * DH4 + l];
            #pragma unroll
            for (int i = 0; i < 8; i++) {
                float2 f0 = __half22float2(r[i].lo);
                float2 f1 = __half22float2(r[i].hi);
                a.x += f0.x; a.y += f0.y; a.z += f1.x; a.w += f1.y;
            }
        }

        float  nd = g_norm_dst[n];
        float4 bv = b[l];
        float v0 = fmaxf(fmaf(a.x, nd, bv.x), 0.f);
        float v1 = fmaxf(fmaf(a.y, nd, bv.y), 0.f);
        float v2 = fmaxf(fmaf(a.z, nd, bv.z), 0.f);
        float v3 = fmaxf(fmaf(a.w, nd, bv.w), 0.f);

        if (EPI == 0) {
            float ns = g_norm_src[n];            // pre-scale for layer-2 gather
            h4 o;
            o.lo = __floats2half2_rn(v0 * ns, v1 * ns);
            o.hi = __floats2half2_rn(v2 * ns, v3 * ns);
            out[n * DH4 + l] = o;
        } else {
            // non-negative floats: uint ordering == float ordering
            atomicMax(&smax[4 * l + 0], __float_as_uint(v0));
            atomicMax(&smax[4 * l + 1], __float_as_uint(v1));
            atomicMax(&smax[4 * l + 2], __float_as_uint(v2));
            atomicMax(&smax[4 * l + 3], __float_as_uint(v3));
        }
    }

    if (EPI == 1) {
        __syncthreads();
        if (t < D) atomicMax(&g_max[t], smax[t]);
    }
}

// --- head: out[1,2] = gmax @ Wl + bl ----------------------------------------------
__global__ void final_kernel(const float* __restrict__ Wl,
                             const float* __restrict__ bl,
                             float* __restrict__ out) {
    int c = threadIdx.x;
    if (c < 2) {
        float acc = bl[c];
        #pragma unroll 8
        for (int k = 0; k < D; k++)
            acc += __uint_as_float(g_max[k]) * Wl[k * 2 + c];
        out[c] = acc;
    }
}

extern "C" void kernel_launch(void* const* d_in, const int* in_sizes, int n_in,
                              void* d_out, int out_size) {
    const float* x   = (const float*)d_in[0];
    const int*   src = (const int*)  d_in[1];
    const int*   dst = (const int*)  d_in[2];
    const float* W1  = (const float*)d_in[3];
    const float* b1  = (const float*)d_in[4];
    const float* W2  = (const float*)d_in[5];
    const float* b2  = (const float*)d_in[6];
    const float* Wl  = (const float*)d_in[7];
    const float* bl  = (const float*)d_in[8];
    float* out = (float*)d_out;

    void *pxw, *ph1, *pdo, *pfill;
    cudaGetSymbolAddress(&pxw,   g_xw);
    cudaGetSymbolAddress(&ph1,   g_h1);
    cudaGetSymbolAddress(&pdo,   g_degi_out);
    cudaGetSymbolAddress(&pfill, g_fill);
    __half* xw = (__half*)pxw;
    __half* h1 = (__half*)ph1;

    int mblocks = (NN + 63) / 64;
    int gblocks = (NN * DH4 + 255) / 256;    // one thread per (node, h4-lane)

    // Scan-free CSR build: one edge pass + one node pass
    cudaMemsetAsync(pdo,   0, NN * sizeof(int));
    cudaMemsetAsync(pfill, 0, NN * sizeof(int));
    fill_kernel    <<<(NE + 255) / 256, 256>>>(src, dst);
    norm_pad_kernel<<<(NN + 255) / 256, 256>>>();

    // Layer 1: xw = (x@W1)*ns (HMMA, fp16);  h1 = relu(nd*gather(xw)+b1)*ns
    dense_mma<0><<<mblocks, 128>>>(x, W1, xw);
    gather_kernel<0><<<gblocks, 256>>>((const h4*)xw, (const float4*)b1, (h4*)h1);

    // Layer 2: xw = h1@W2 (HMMA); gather + fused maxpool
    dense_mma<1><<<mblocks, 128>>>(h1, W2, xw);
    gather_kernel<1><<<gblocks, 256>>>((const h4*)xw, (const float4*)b2, nullptr);

    final_kernel<<<1, 32>>>(Wl, bl, out);
}

// round 17
// speedup vs baseline: 1.2303x; 1.0762x over previous
#include <cuda_runtime.h>
#include <cuda_fp16.h>
#include <cstdint>

// ---------------------------------------------------------------------------
// GCN_dgl R15: R14 + wide gather (12 threads/node, 16B row loads) + head
// fused into gather<1> via last-block ticket. Scan-free u16 buckets, HMMA
// dense (ns epilogue in MODE 0), fp16 intermediates, tail-free loops.
// ---------------------------------------------------------------------------

constexpr int NN  = 50000;
constexpr int NE  = 800000;
constexpr int D   = 96;
constexpr int DU4 = D / 8;                 // 12 uint4-lanes per fp16 row (16B)
constexpr int LDS = 104;                   // smem half-stride for MMA tiles
constexpr int CAP = 128;                   // bucket capacity (max in-deg ~45)

// Scratch (allocation-free __device__ globals; zero-initialized at load)
__device__ int          g_degi_out[NN];
__device__ float        g_norm_src[NN + 1];   // [NN] stays 0 forever (dummy row)
__device__ float        g_norm_dst[NN];
__device__ int          g_fill[NN];           // slot counter == in-degree
__device__ alignas(16) unsigned short g_csr[(size_t)NN * CAP];
__device__ __half       g_xw[(size_t)(NN + 1) * D];  // row NN: permanent zeros
__device__ __half       g_h1[(size_t)(NN + 1) * D];  // row NN: permanent zeros
__device__ unsigned int g_max[D];
__device__ int          g_done;               // last-block ticket (self-resetting)

// --- mma/ldmatrix primitives --------------------------------------------------
__device__ __forceinline__ void ldsm_x4(uint32_t& r0, uint32_t& r1, uint32_t& r2,
                                        uint32_t& r3, uint32_t addr) {
    asm volatile("ldmatrix.sync.aligned.m8n8.x4.shared.b16 {%0,%1,%2,%3}, [%4];"
                 : "=r"(r0), "=r"(r1), "=r"(r2), "=r"(r3) : "r"(addr));
}
__device__ __forceinline__ void ldsm_x2_trans(uint32_t& r0, uint32_t& r1, uint32_t addr) {
    asm volatile("ldmatrix.sync.aligned.m8n8.x2.trans.shared.b16 {%0,%1}, [%2];"
                 : "=r"(r0), "=r"(r1) : "r"(addr));
}
__device__ __forceinline__ void mma16816(float& d0, float& d1, float& d2, float& d3,
                                         uint32_t a0, uint32_t a1, uint32_t a2,
                                         uint32_t a3, uint32_t b0, uint32_t b1) {
    asm volatile(
        "mma.sync.aligned.m16n8k16.row.col.f32.f16.f16.f32 "
        "{%0,%1,%2,%3},{%4,%5,%6,%7},{%8,%9},{%0,%1,%2,%3};"
        : "+f"(d0), "+f"(d1), "+f"(d2), "+f"(d3)
        : "r"(a0), "r"(a1), "r"(a2), "r"(a3), "r"(b0), "r"(b1));
}

// --- accumulate 8 halves (one uint4) into 8 fp32 accumulators -------------------
__device__ __forceinline__ void acc8(float* a, uint4 r) {
    float2 f;
    f = __half22float2(*(__half2*)&r.x); a[0] += f.x; a[1] += f.y;
    f = __half22float2(*(__half2*)&r.y); a[2] += f.x; a[3] += f.y;
    f = __half22float2(*(__half2*)&r.z); a[4] += f.x; a[5] += f.y;
    f = __half22float2(*(__half2*)&r.w); a[6] += f.x; a[7] += f.y;
}

// --- single edge pass: bucket slot allocation + both degree counts --------------
__global__ void fill_kernel(const int* __restrict__ src, const int* __restrict__ dst) {
    int e = blockIdx.x * blockDim.x + threadIdx.x;
    if (e < NE) {
        int s = src[e];
        int d = dst[e];
        int pos = atomicAdd(&g_fill[d], 1);            // counter == in-degree
        if (pos < CAP) g_csr[(size_t)d * CAP + pos] = (unsigned short)s;
        atomicAdd(&g_degi_out[s], 1);                  // out-degree for norm_src
    }
}

// --- norms from the counters + pad dummy slots to a multiple of 8 ---------------
__global__ void norm_pad_kernel() {
    int i = blockIdx.x * blockDim.x + threadIdx.x;
    if (i < D) g_max[i] = 0u;                 // consumed by gather<1> (later)
    if (i < NN) {
        int dI = g_fill[i]; if (dI > CAP) dI = CAP;
        int dO = g_degi_out[i];
        g_norm_src[i] = (dO > 0) ? rsqrtf((float)dO) : 1.0f;
        g_norm_dst[i] = (dI > 0) ? rsqrtf((float)dI) : 1.0f;
        int pdeg = (dI + 7) & ~7;             // pad [dI, pdeg) with zero-row idx
        size_t base = (size_t)i * CAP;
        for (int s = dI; s < pdeg; s++) g_csr[base + s] = (unsigned short)NN;
    }
}

// --- tensor-core dense GEMM: out_h = (in @ W) [* norm_src] -----------------------
// MODE 0: fp32 input (x), epilogue scales rows by norm_src. MODE 1: fp16 input.
template <int MODE>
__global__ void __launch_bounds__(128)
dense_mma(const void* __restrict__ in_, const float* __restrict__ W,
          __half* __restrict__ out) {
    __shared__ alignas(16) __half Bs[96 * LDS];
    __shared__ alignas(16) __half As[4][16 * LDS];

    int tid = threadIdx.x, wid = tid >> 5, lane = tid & 31;

    for (int c = tid; c < 96 * 12; c += 128) {
        int r = c / 12, c8 = c % 12;
        const float4* wp = (const float4*)(W + r * 96 + c8 * 8);
        float4 f0 = wp[0], f1 = wp[1];
        __half hb[8] = {__float2half_rn(f0.x), __float2half_rn(f0.y),
                        __float2half_rn(f0.z), __float2half_rn(f0.w),
                        __float2half_rn(f1.x), __float2half_rn(f1.y),
                        __float2half_rn(f1.z), __float2half_rn(f1.w)};
        *(uint4*)&Bs[r * LDS + c8 * 8] = *(uint4*)hb;
    }

    int rowBase = blockIdx.x * 64 + wid * 16;
    for (int c = lane; c < 16 * 12; c += 32) {
        int r = c / 12, c8 = c % 12;
        int n = rowBase + r;
        __half hb[8];
        if (n < NN) {
            if (MODE == 0) {
                const float4* xp = (const float4*)((const float*)in_ + (size_t)n * D + c8 * 8);
                float4 f0 = xp[0], f1 = xp[1];
                hb[0] = __float2half_rn(f0.x); hb[1] = __float2half_rn(f0.y);
                hb[2] = __float2half_rn(f0.z); hb[3] = __float2half_rn(f0.w);
                hb[4] = __float2half_rn(f1.x); hb[5] = __float2half_rn(f1.y);
                hb[6] = __float2half_rn(f1.z); hb[7] = __float2half_rn(f1.w);
            } else {
                *(uint4*)hb = *(const uint4*)((const __half*)in_ + (size_t)n * D + c8 * 8);
            }
        } else {
            #pragma unroll
            for (int q = 0; q < 8; q++) hb[q] = __float2half_rn(0.f);
        }
        *(uint4*)&As[wid][r * LDS + c8 * 8] = *(uint4*)hb;
    }
    __syncthreads();

    float d[12][4];
    #pragma unroll
    for (int j = 0; j < 12; j++) { d[j][0] = d[j][1] = d[j][2] = d[j][3] = 0.f; }

    uint32_t aBase = (uint32_t)__cvta_generic_to_shared(&As[wid][0]);
    uint32_t bBase = (uint32_t)__cvta_generic_to_shared(&Bs[0]);

    #pragma unroll
    for (int k = 0; k < 6; k++) {
        uint32_t a0, a1, a2, a3;
        uint32_t aAddr = aBase + (uint32_t)(((lane & 15) * LDS + (lane >> 4) * 8 + k * 16) * 2);
        ldsm_x4(a0, a1, a2, a3, aAddr);
        #pragma unroll
        for (int j = 0; j < 12; j++) {
            uint32_t b0, b1;
            uint32_t bAddr = bBase + (uint32_t)(((k * 16 + (lane & 15)) * LDS + j * 8) * 2);
            ldsm_x2_trans(b0, b1, bAddr);
            mma16816(d[j][0], d[j][1], d[j][2], d[j][3], a0, a1, a2, a3, b0, b1);
        }
    }

    int g = lane >> 2, q = lane & 3;
    int r0 = rowBase + g, r1 = rowBase + g + 8;
    float ns0 = 1.f, ns1 = 1.f;
    if (MODE == 0) {
        if (r0 < NN) ns0 = g_norm_src[r0];
        if (r1 < NN) ns1 = g_norm_src[r1];
    }
    #pragma unroll
    for (int j = 0; j < 12; j++) {
        int col = j * 8 + q * 2;
        if (r0 < NN)
            *(__half2*)&out[(size_t)r0 * D + col] = __floats2half2_rn(d[j][0] * ns0, d[j][1] * ns0);
        if (r1 < NN)
            *(__half2*)&out[(size_t)r1 * D + col] = __floats2half2_rn(d[j][2] * ns1, d[j][3] * ns1);
    }
}

// --- wide full-lane gather: 12 threads/node, one uint4 (8 features) each --------
// Buckets padded to multiples of 8 (dummy idx NN -> permanently-zero row).
// EPI 0: out[n] = relu(agg*nd + b) * ns[n]  (fp16)
// EPI 1: relu(agg*nd + b) -> smem max -> g_max; LAST BLOCK computes the head:
//        outp[1,2] = gmax @ Wl + bl  (ticket in g_done, self-resetting).
template <int EPI>
__global__ void __launch_bounds__(256)
gather_kernel(const uint4* __restrict__ in, const float* __restrict__ b,
              uint4* __restrict__ out,
              const float* __restrict__ Wl, const float* __restrict__ bl,
              float* __restrict__ outp) {
    __shared__ unsigned int smax[D];
    __shared__ int isLast;
    int t = threadIdx.x;
    if (EPI == 1) {
        if (t < D) smax[t] = 0u;
        __syncthreads();
    }

    int gid = blockIdx.x * 256 + t;
    int n   = gid / DU4;                     // 12 threads per node
    int l   = gid - n * DU4;                 // uint4 lane (8 features)

    if (n < NN) {
        int dI = g_fill[n]; if (dI > CAP) dI = CAP;
        int pdeg = (dI + 7) & ~7;
        const unsigned short* bucket = g_csr + (size_t)n * CAP;
        float a[8];
        #pragma unroll
        for (int i = 0; i < 8; i++) a[i] = 0.f;

        for (int p = 0; p < pdeg; p += 8) {      // 8 u16 indices = one LDG.128
            uint4 q = *(const uint4*)(bucket + p);
            int s0 = (int)(q.x & 0xffffu), s1 = (int)(q.x >> 16);
            int s2 = (int)(q.y & 0xffffu), s3 = (int)(q.y >> 16);
            int s4 = (int)(q.z & 0xffffu), s5 = (int)(q.z >> 16);
            int s6 = (int)(q.w & 0xffffu), s7 = (int)(q.w >> 16);
            {   // 4-edge sub-batch (keeps live row regs at 16)
                uint4 r0 = in[s0 * DU4 + l];
                uint4 r1 = in[s1 * DU4 + l];
                uint4 r2 = in[s2 * DU4 + l];
                uint4 r3 = in[s3 * DU4 + l];
                acc8(a, r0); acc8(a, r1); acc8(a, r2); acc8(a, r3);
            }
            {
                uint4 r0 = in[s4 * DU4 + l];
                uint4 r1 = in[s5 * DU4 + l];
                uint4 r2 = in[s6 * DU4 + l];
                uint4 r3 = in[s7 * DU4 + l];
                acc8(a, r0); acc8(a, r1); acc8(a, r2); acc8(a, r3);
            }
        }

        float nd = g_norm_dst[n];
        float v[8];
        #pragma unroll
        for (int i = 0; i < 8; i++)
            v[i] = fmaxf(fmaf(a[i], nd, b[8 * l + i]), 0.f);

        if (EPI == 0) {
            float ns = g_norm_src[n];            // pre-scale for layer-2 gather
            uint4 o;
            *(__half2*)&o.x = __floats2half2_rn(v[0] * ns, v[1] * ns);
            *(__half2*)&o.y = __floats2half2_rn(v[2] * ns, v[3] * ns);
            *(__half2*)&o.z = __floats2half2_rn(v[4] * ns, v[5] * ns);
            *(__half2*)&o.w = __floats2half2_rn(v[6] * ns, v[7] * ns);
            out[n * DU4 + l] = o;
        } else {
            // non-negative floats: uint ordering == float ordering
            #pragma unroll
            for (int i = 0; i < 8; i++)
                atomicMax(&smax[8 * l + i], __float_as_uint(v[i]));
        }
    }

    if (EPI == 1) {
        __syncthreads();
        if (t < D) atomicMax(&g_max[t], smax[t]);
        __syncthreads();
        if (t == 0) {
            __threadfence();
            int ticket = atomicAdd(&g_done, 1);
            isLast = (ticket == (int)gridDim.x - 1);
        }
        __syncthreads();
        if (isLast) {
            __threadfence();
            if (t < 2) {
                float acc = bl[t];
                #pragma unroll 8
                for (int k = 0; k < D; k++)
                    acc += __uint_as_float(g_max[k]) * Wl[k * 2 + t];
                outp[t] = acc;
            }
            if (t == 0) g_done = 0;          // reset for next graph replay
        }
    }
}

extern "C" void kernel_launch(void* const* d_in, const int* in_sizes, int n_in,
                              void* d_out, int out_size) {
    const float* x   = (const float*)d_in[0];
    const int*   src = (const int*)  d_in[1];
    const int*   dst = (const int*)  d_in[2];
    const float* W1  = (const float*)d_in[3];
    const float* b1  = (const float*)d_in[4];
    const float* W2  = (const float*)d_in[5];
    const float* b2  = (const float*)d_in[6];
    const float* Wl  = (const float*)d_in[7];
    const float* bl  = (const float*)d_in[8];
    float* out = (float*)d_out;

    void *pxw, *ph1, *pdo, *pfill;
    cudaGetSymbolAddress(&pxw,   g_xw);
    cudaGetSymbolAddress(&ph1,   g_h1);
    cudaGetSymbolAddress(&pdo,   g_degi_out);
    cudaGetSymbolAddress(&pfill, g_fill);
    __half* xw = (__half*)pxw;
    __half* h1 = (__half*)ph1;

    int mblocks = (NN + 63) / 64;
    int gblocks = (NN * DU4 + 255) / 256;    // one thread per (node, uint4-lane)

    // Scan-free CSR build: one edge pass + one node pass
    cudaMemsetAsync(pdo,   0, NN * sizeof(int));
    cudaMemsetAsync(pfill, 0, NN * sizeof(int));
    fill_kernel    <<<(NE + 255) / 256, 256>>>(src, dst);
    norm_pad_kernel<<<(NN + 255) / 256, 256>>>();

    // Layer 1: xw = (x@W1)*ns (HMMA, fp16);  h1 = relu(nd*gather(xw)+b1)*ns
    dense_mma<0><<<mblocks, 128>>>(x, W1, xw);
    gather_kernel<0><<<gblocks, 256>>>((const uint4*)xw, b1, (uint4*)h1,
                                       nullptr, nullptr, nullptr);

    // Layer 2: xw = h1@W2 (HMMA); gather + fused maxpool + fused head
    dense_mma<1><<<mblocks, 128>>>(h1, W2, xw);
    gather_kernel<1><<<gblocks, 256>>>((const uint4*)xw, b2, nullptr,
                                       Wl, bl, out);
}